// round 14
// baseline (speedup 1.0000x reference)
#include <cuda_runtime.h>
#include <cuda_fp16.h>

#define Bn 16
#define Cc 256
#define NH 8
#define HD 32
#define SQ 1024
#define TQ 128
#define TK 64
#define NIT (SQ / TK)
#define QSCALE 0.25507021480342156f /* 32^-0.5 * log2(e) */
#define MFIX 12.0f                  /* fixed softmax bias (log2 domain) */

// conv outputs, fp16
__device__ __half g_kh[Bn * SQ * Cc];
__device__ __half g_vh[Bn * SQ * Cc];

// ---------------------------------------------------------------------------
// Depthwise dilated 3x3 conv (dilation 2, SAME). Each thread computes
// 4 channels x 4 y-outputs (same parity, step 2).
// ---------------------------------------------------------------------------
__global__ __launch_bounds__(256) void dwconv_kernel(
    const float* __restrict__ kin,
    const float* __restrict__ vin,
    const float* __restrict__ ker,     // [3,3,1,C]
    const float* __restrict__ bias) {  // [C]
    int t    = blockIdx.x * 256 + threadIdx.x;
    int c    = (t & 63) * 4;
    int idx2 = t >> 6;
    int x  = idx2 & 31;
    int yg = (idx2 >> 5) & 7;
    int b  = idx2 >> 8;
    int p  = yg & 1;
    int g  = yg >> 1;

    float4 w[9];
#pragma unroll
    for (int ti = 0; ti < 9; ti++) w[ti] = *(const float4*)(ker + ti * Cc + c);
    float4 bi = *(const float4*)(bias + c);
    float4 ka[4], va[4];
#pragma unroll
    for (int i = 0; i < 4; i++) { ka[i] = bi; va[i] = bi; }

#pragma unroll
    for (int j = 0; j < 3; j++) {
        int xx = x + 2 * j - 2;
        if ((unsigned)xx >= 32u) continue;
#pragma unroll
        for (int r = 0; r < 6; r++) {
            int ry = 4 * g + r - 1;
            if ((unsigned)ry >= 16u) continue;
            int yy = p + 2 * ry;
            size_t idx = ((size_t)((b * 32 + yy) * 32 + xx)) * Cc + c;
            float4 kv = *(const float4*)(kin + idx);
            float4 vv = *(const float4*)(vin + idx);
#pragma unroll
            for (int i = 0; i < 4; i++) {
                int ti = r - i;
                if (ti < 0 || ti > 2) continue;
                float4 ww = w[ti * 3 + j];
                ka[i].x = fmaf(kv.x, ww.x, ka[i].x);
                ka[i].y = fmaf(kv.y, ww.y, ka[i].y);
                ka[i].z = fmaf(kv.z, ww.z, ka[i].z);
                ka[i].w = fmaf(kv.w, ww.w, ka[i].w);
                va[i].x = fmaf(vv.x, ww.x, va[i].x);
                va[i].y = fmaf(vv.y, ww.y, va[i].y);
                va[i].z = fmaf(vv.z, ww.z, va[i].z);
                va[i].w = fmaf(vv.w, ww.w, va[i].w);
            }
        }
    }
#pragma unroll
    for (int i = 0; i < 4; i++) {
        int yy = p + 2 * (4 * g + i);
        size_t o = ((size_t)(b * 1024 + yy * 32 + x)) * Cc + c;
        __half2 k0 = __floats2half2_rn(ka[i].x, ka[i].y);
        __half2 k1 = __floats2half2_rn(ka[i].z, ka[i].w);
        __half2 v0 = __floats2half2_rn(va[i].x, va[i].y);
        __half2 v1 = __floats2half2_rn(va[i].z, va[i].w);
        *(__half2*)(g_kh + o)     = k0;
        *(__half2*)(g_kh + o + 2) = k1;
        *(__half2*)(g_vh + o)     = v0;
        *(__half2*)(g_vh + o + 2) = v1;
    }
}

// ---------------------------------------------------------------------------
#define MMA16816(d0, d1, d2, d3, a0, a1, a2, a3, b0, b1)                      \
    asm volatile(                                                             \
        "mma.sync.aligned.m16n8k16.row.col.f32.f16.f16.f32 "                  \
        "{%0,%1,%2,%3},{%4,%5,%6,%7},{%8,%9},{%0,%1,%2,%3};\n"                \
        : "+f"(d0), "+f"(d1), "+f"(d2), "+f"(d3)                              \
        : "r"(a0), "r"(a1), "r"(a2), "r"(a3), "r"(b0), "r"(b1))

#define LDSM4(r0, r1, r2, r3, addr)                                           \
    asm volatile(                                                             \
        "ldmatrix.sync.aligned.m8n8.x4.shared.b16 {%0,%1,%2,%3},[%4];\n"      \
        : "=r"(r0), "=r"(r1), "=r"(r2), "=r"(r3)                              \
        : "r"(addr))

#define LDSM4T(r0, r1, r2, r3, addr)                                          \
    asm volatile(                                                             \
        "ldmatrix.sync.aligned.m8n8.x4.trans.shared.b16 {%0,%1,%2,%3},[%4];\n"\
        : "=r"(r0), "=r"(r1), "=r"(r2), "=r"(r3)                              \
        : "r"(addr))

#define CP16(d, s)                                                            \
    asm volatile("cp.async.cg.shared.global [%0], [%1], 16;\n"                \
                 :: "r"(d), "l"(s))
#define CPCOMMIT asm volatile("cp.async.commit_group;\n")
#define CPWAIT1  asm volatile("cp.async.wait_group 1;\n")
#define CPWAIT0  asm volatile("cp.async.wait_group 0;\n")

__device__ __forceinline__ float ex2f(float x) {
    float r;
    asm("ex2.approx.ftz.f32 %0, %1;" : "=f"(r) : "f"(x));
    return r;
}

#define ONESH2 0x3C003C00u   /* half2 {1.0, 1.0} */
#define LDS 40               /* smem row stride in halfs (80B) */
#define STG_B (TK * LDS * 2) /* bytes per K/V stage: 5120 */

__global__ __launch_bounds__(256, 3) void attn_kernel(
    const float* __restrict__ q,   // [B, S, C] fp32
    float* __restrict__ out) {     // [B, S, C] fp32
    int qt = blockIdx.x, h = blockIdx.y, b = blockIdx.z;

    __shared__ __align__(16) __half Qs[TQ * LDS];
    __shared__ __align__(16) __half Ks[3][TK * LDS];
    __shared__ __align__(16) __half Vh[3][TK * LDS];

    int tid  = threadIdx.x;
    int warp = tid >> 5;
    int lane = tid & 31;
    int ln   = lane >> 2;
    int lq   = (lane & 3) * 2;

    const __half* kg = g_kh + (size_t)b * SQ * Cc + h * HD;
    const __half* vg = g_vh + (size_t)b * SQ * Cc + h * HD;

    // ---- cp.async staging ----
    int srow = tid >> 2;
    int scol = (tid & 3) * 8;
    unsigned dk0 = (unsigned)__cvta_generic_to_shared(&Ks[0][srow * LDS + scol]);
    unsigned dv0 = (unsigned)__cvta_generic_to_shared(&Vh[0][srow * LDS + scol]);

    // prefetch tiles 0 and 1
    {
        size_t g0 = (size_t)srow * Cc + scol;
        CP16(dk0, kg + g0);
        CP16(dv0, vg + g0);
        CPCOMMIT;
        size_t g1 = ((size_t)(TK + srow)) * Cc + scol;
        CP16(dk0 + STG_B, kg + g1);
        CP16(dv0 + STG_B, vg + g1);
        CPCOMMIT;
    }

    // ---- load Q tile ----
    const float* qg = q + ((size_t)(b * SQ + qt * TQ)) * Cc + h * HD;
#pragma unroll
    for (int i = 0; i < 4; i++) {
        int idx = tid + i * 256;
        int r = idx >> 3, cp = (idx & 7) * 4;
        float4 v = *(const float4*)(qg + (size_t)r * Cc + cp);
        __half2 h0 = __floats2half2_rn(v.x * QSCALE, v.y * QSCALE);
        __half2 h1 = __floats2half2_rn(v.z * QSCALE, v.w * QSCALE);
        *(__half2*)&Qs[r * LDS + cp]     = h0;
        *(__half2*)&Qs[r * LDS + cp + 2] = h1;
    }
    __syncthreads();

    // ---- Q A-frags ----
    unsigned qa[2][4];
    {
        int r0 = warp * 16 + ln;
#pragma unroll
        for (int s = 0; s < 2; s++) {
            qa[s][0] = *(const unsigned*)&Qs[r0 * LDS + lq + s * 16];
            qa[s][1] = *(const unsigned*)&Qs[(r0 + 8) * LDS + lq + s * 16];
            qa[s][2] = *(const unsigned*)&Qs[r0 * LDS + lq + 8 + s * 16];
            qa[s][3] = *(const unsigned*)&Qs[(r0 + 8) * LDS + lq + 8 + s * 16];
        }
    }

    // ---- ldmatrix bases (stage 0) ----
    int krow = ((lane >> 4) << 3) + (lane & 7);
    int kcol = ((lane >> 3) & 1) * 8;
    unsigned kfb0 = (unsigned)__cvta_generic_to_shared(&Ks[0][krow * LDS + kcol]);
    int mi  = lane >> 3;
    int vro = ((mi & 1) << 3) + (lane & 7);
    int vco = (mi >> 1) << 3;
    unsigned vfb0 = (unsigned)__cvta_generic_to_shared(&Vh[0][vro * LDS + vco]);

    float oc[4][4] = {};
    float lc[4]    = {};
    float mr0, mr1;                 // row-max bias (set in peeled tile 0)
    int cur, pre;

#define QKS(jp, s)                                                            \
    do {                                                                      \
        unsigned b0, b1, b2, b3;                                              \
        LDSM4(b0, b1, b2, b3,                                                 \
              kf + (unsigned)((jp) * (16 * LDS * 2) + (s) * 32));             \
        MMA16816(sc[2*(jp)][0], sc[2*(jp)][1], sc[2*(jp)][2], sc[2*(jp)][3],  \
                 qa[s][0], qa[s][1], qa[s][2], qa[s][3], b0, b1);             \
        MMA16816(sc[2*(jp)+1][0], sc[2*(jp)+1][1], sc[2*(jp)+1][2],           \
                 sc[2*(jp)+1][3],                                             \
                 qa[s][0], qa[s][1], qa[s][2], qa[s][3], b2, b3);             \
    } while (0)

/* f32 exp (tile 0 only), centered by freshly computed row max */
#define EXPT0(t)                                                              \
    do {                                                                      \
        float e0 = ex2f(sc[2*(t)][0] - mr0);                                  \
        float e1 = ex2f(sc[2*(t)][1] - mr0);                                  \
        float e2 = ex2f(sc[2*(t)][2] - mr1);                                  \
        float e3 = ex2f(sc[2*(t)][3] - mr1);                                  \
        float g0 = ex2f(sc[2*(t)+1][0] - mr0);                                \
        float g1 = ex2f(sc[2*(t)+1][1] - mr0);                                \
        float g2 = ex2f(sc[2*(t)+1][2] - mr1);                                \
        float g3 = ex2f(sc[2*(t)+1][3] - mr1);                                \
        __half2 d;                                                            \
        d = __floats2half2_rn(e0, e1); pa[t][0] = *(unsigned*)&d;             \
        d = __floats2half2_rn(e2, e3); pa[t][1] = *(unsigned*)&d;             \
        d = __floats2half2_rn(g0, g1); pa[t][2] = *(unsigned*)&d;             \
        d = __floats2half2_rn(g2, g3); pa[t][3] = *(unsigned*)&d;             \
    } while (0)

/* fp16x2 exp (tiles 1..): args centered near 0 by mr -> fp16-safe;
   centering FADD runs on the idle fma pipe; MUFU count halved */
#define EXPTH(t)                                                              \
    do {                                                                      \
        __half2 d;                                                            \
        d = h2exp2(__floats2half2_rn(sc[2*(t)][0] - mr0, sc[2*(t)][1] - mr0));\
        pa[t][0] = *(unsigned*)&d;                                            \
        d = h2exp2(__floats2half2_rn(sc[2*(t)][2] - mr1, sc[2*(t)][3] - mr1));\
        pa[t][1] = *(unsigned*)&d;                                            \
        d = h2exp2(__floats2half2_rn(sc[2*(t)+1][0] - mr0,                    \
                                     sc[2*(t)+1][1] - mr0));                  \
        pa[t][2] = *(unsigned*)&d;                                            \
        d = h2exp2(__floats2half2_rn(sc[2*(t)+1][2] - mr1,                    \
                                     sc[2*(t)+1][3] - mr1));                  \
        pa[t][3] = *(unsigned*)&d;                                            \
    } while (0)

#define LMMA(t)                                                               \
    MMA16816(lc[0], lc[1], lc[2], lc[3],                                      \
             pa[t][0], pa[t][1], pa[t][2], pa[t][3], ONESH2, ONESH2)

#define PVT(pair, t)                                                          \
    do {                                                                      \
        unsigned r0, r1, r2, r3;                                              \
        LDSM4T(r0, r1, r2, r3,                                                \
               vf + (unsigned)((t) * (16 * LDS * 2) + (pair) * 32));          \
        MMA16816(oc[2*(pair)][0], oc[2*(pair)][1], oc[2*(pair)][2],           \
                 oc[2*(pair)][3],                                             \
                 pa[t][0], pa[t][1], pa[t][2], pa[t][3], r0, r1);             \
        MMA16816(oc[2*(pair)+1][0], oc[2*(pair)+1][1], oc[2*(pair)+1][2],     \
                 oc[2*(pair)+1][3],                                           \
                 pa[t][0], pa[t][1], pa[t][2], pa[t][3], r2, r3);             \
    } while (0)

#define PVBLOCK                                                               \
    do {                                                                      \
        PVT(0, 0); PVT(1, 0); LMMA(0);                                        \
        PVT(0, 1); PVT(1, 1); LMMA(1);                                        \
        PVT(0, 2); PVT(1, 2); LMMA(2);                                        \
        PVT(0, 3); PVT(1, 3); LMMA(3);                                        \
    } while (0)

    // ================= peeled tile 0 (computes row-max bias) =================
    {
        CPWAIT1;
        __syncthreads();
        // prefetch tile 2 into stage 2
        {
            size_t go = ((size_t)(2 * TK + srow)) * Cc + scol;
            CP16(dk0 + 2 * STG_B, kg + go);
            CP16(dv0 + 2 * STG_B, vg + go);
            CPCOMMIT;
        }
        unsigned kf = kfb0;
        unsigned vf = vfb0;

        float sc[8][4];
#pragma unroll
        for (int j = 0; j < 8; j++)
#pragma unroll
            for (int c = 0; c < 4; c++) sc[j][c] = -MFIX;
        unsigned pa[4][4];

        QKS(0, 0); QKS(1, 0); QKS(2, 0); QKS(3, 0);
        QKS(0, 1); QKS(1, 1); QKS(2, 1); QKS(3, 1);

        float mx0 = -1e30f, mx1 = -1e30f;
#pragma unroll
        for (int j = 0; j < 8; j++) {
            mx0 = fmaxf(mx0, fmaxf(sc[j][0], sc[j][1]));
            mx1 = fmaxf(mx1, fmaxf(sc[j][2], sc[j][3]));
        }
        mx0 = fmaxf(mx0, __shfl_xor_sync(0xffffffffu, mx0, 1));
        mx0 = fmaxf(mx0, __shfl_xor_sync(0xffffffffu, mx0, 2));
        mx1 = fmaxf(mx1, __shfl_xor_sync(0xffffffffu, mx1, 1));
        mx1 = fmaxf(mx1, __shfl_xor_sync(0xffffffffu, mx1, 2));
        mr0 = mx0; mr1 = mx1;

        EXPT0(0); EXPT0(1); EXPT0(2); EXPT0(3);
        PVBLOCK;
        cur = 1; pre = 0;
    }

    // ================= main loop: tiles 1..15, branchless =================
    for (int kt = 1; kt < NIT; kt++) {
        if (kt == NIT - 1) { CPWAIT0; } else { CPWAIT1; }
        __syncthreads();   // tile kt visible; stage 'pre' readers done

        if (kt + 2 < NIT) {
            size_t go = ((size_t)((kt + 2) * TK + srow)) * Cc + scol;
            unsigned off = (unsigned)(pre * STG_B);
            CP16(dk0 + off, kg + go);
            CP16(dv0 + off, vg + go);
            CPCOMMIT;
        }
        unsigned kf = kfb0 + (unsigned)(cur * STG_B);
        unsigned vf = vfb0 + (unsigned)(cur * STG_B);

        float sc[8][4];
#pragma unroll
        for (int j = 0; j < 8; j++)
#pragma unroll
            for (int c = 0; c < 4; c++) sc[j][c] = -MFIX;
        unsigned pa[4][4];

        // ---- QK: s-outer (same-accumulator distance 8), exps threaded ----
        QKS(0, 0); QKS(1, 0); QKS(2, 0); QKS(3, 0);
        QKS(0, 1); QKS(1, 1);
        EXPTH(0);
        QKS(2, 1);
        EXPTH(1);
        QKS(3, 1);
        EXPTH(2);
        EXPTH(3);

        PVBLOCK;

        cur = (cur == 2) ? 0 : cur + 1;
        pre = (pre == 2) ? 0 : pre + 1;
    }

    // ---- epilogue (2^-(MFIX+mr) factor cancels in oc/lc) ----
    float il0 = 1.0f / lc[0];
    float il1 = 1.0f / lc[2];
    int gr0 = qt * TQ + warp * 16 + ln;
    size_t ob = ((size_t)b * SQ) * Cc + h * HD;
#pragma unroll
    for (int n = 0; n < 4; n++) {
        int c0 = n * 8 + lq;
        float2 v0 = make_float2(oc[n][0] * il0, oc[n][1] * il0);
        float2 v1 = make_float2(oc[n][2] * il1, oc[n][3] * il1);
        *(float2*)&out[ob + (size_t)gr0 * Cc + c0]       = v0;
        *(float2*)&out[ob + (size_t)(gr0 + 8) * Cc + c0] = v1;
    }
}

// ---------------------------------------------------------------------------
extern "C" void kernel_launch(void* const* d_in, const int* in_sizes, int n_in,
                              void* d_out, int out_size) {
    const float* query  = (const float*)d_in[0];
    const float* key_in = (const float*)d_in[1];
    const float* value  = (const float*)d_in[2];
    const float* ck     = (const float*)d_in[3];
    const float* cb     = (const float*)d_in[4];
    float* out = (float*)d_out;

    dwconv_kernel<<<1024, 256>>>(key_in, value, ck, cb);

    dim3 grid(SQ / TQ, NH, Bn);
    attn_kernel<<<grid, 256>>>(query, out);
}

// round 15
// speedup vs baseline: 1.6624x; 1.6624x over previous
#include <cuda_runtime.h>
#include <cuda_fp16.h>

#define Bn 16
#define Cc 256
#define NH 8
#define HD 32
#define SQ 1024
#define TQ 128
#define TK 64
#define NIT (SQ / TK)
#define QSCALE 0.25507021480342156f /* 32^-0.5 * log2(e) */
#define MFIX 12.0f                  /* fixed softmax bias (log2 domain) */

// conv outputs, fp16
__device__ __half g_kh[Bn * SQ * Cc];
__device__ __half g_vh[Bn * SQ * Cc];

// ---------------------------------------------------------------------------
// Depthwise dilated 3x3 conv (dilation 2, SAME). Each thread computes
// 4 channels x 4 y-outputs (same parity, step 2).
// ---------------------------------------------------------------------------
__global__ __launch_bounds__(256) void dwconv_kernel(
    const float* __restrict__ kin,
    const float* __restrict__ vin,
    const float* __restrict__ ker,     // [3,3,1,C]
    const float* __restrict__ bias) {  // [C]
    int t    = blockIdx.x * 256 + threadIdx.x;
    int c    = (t & 63) * 4;
    int idx2 = t >> 6;
    int x  = idx2 & 31;
    int yg = (idx2 >> 5) & 7;
    int b  = idx2 >> 8;
    int p  = yg & 1;
    int g  = yg >> 1;

    float4 w[9];
#pragma unroll
    for (int ti = 0; ti < 9; ti++) w[ti] = *(const float4*)(ker + ti * Cc + c);
    float4 bi = *(const float4*)(bias + c);
    float4 ka[4], va[4];
#pragma unroll
    for (int i = 0; i < 4; i++) { ka[i] = bi; va[i] = bi; }

#pragma unroll
    for (int j = 0; j < 3; j++) {
        int xx = x + 2 * j - 2;
        if ((unsigned)xx >= 32u) continue;
#pragma unroll
        for (int r = 0; r < 6; r++) {
            int ry = 4 * g + r - 1;
            if ((unsigned)ry >= 16u) continue;
            int yy = p + 2 * ry;
            size_t idx = ((size_t)((b * 32 + yy) * 32 + xx)) * Cc + c;
            float4 kv = *(const float4*)(kin + idx);
            float4 vv = *(const float4*)(vin + idx);
#pragma unroll
            for (int i = 0; i < 4; i++) {
                int ti = r - i;
                if (ti < 0 || ti > 2) continue;
                float4 ww = w[ti * 3 + j];
                ka[i].x = fmaf(kv.x, ww.x, ka[i].x);
                ka[i].y = fmaf(kv.y, ww.y, ka[i].y);
                ka[i].z = fmaf(kv.z, ww.z, ka[i].z);
                ka[i].w = fmaf(kv.w, ww.w, ka[i].w);
                va[i].x = fmaf(vv.x, ww.x, va[i].x);
                va[i].y = fmaf(vv.y, ww.y, va[i].y);
                va[i].z = fmaf(vv.z, ww.z, va[i].z);
                va[i].w = fmaf(vv.w, ww.w, va[i].w);
            }
        }
    }
#pragma unroll
    for (int i = 0; i < 4; i++) {
        int yy = p + 2 * (4 * g + i);
        size_t o = ((size_t)(b * 1024 + yy * 32 + x)) * Cc + c;
        __half2 k0 = __floats2half2_rn(ka[i].x, ka[i].y);
        __half2 k1 = __floats2half2_rn(ka[i].z, ka[i].w);
        __half2 v0 = __floats2half2_rn(va[i].x, va[i].y);
        __half2 v1 = __floats2half2_rn(va[i].z, va[i].w);
        *(__half2*)(g_kh + o)     = k0;
        *(__half2*)(g_kh + o + 2) = k1;
        *(__half2*)(g_vh + o)     = v0;
        *(__half2*)(g_vh + o + 2) = v1;
    }
}

// ---------------------------------------------------------------------------
#define MMA16816(d0, d1, d2, d3, a0, a1, a2, a3, b0, b1)                      \
    asm volatile(                                                             \
        "mma.sync.aligned.m16n8k16.row.col.f32.f16.f16.f32 "                  \
        "{%0,%1,%2,%3},{%4,%5,%6,%7},{%8,%9},{%0,%1,%2,%3};\n"                \
        : "+f"(d0), "+f"(d1), "+f"(d2), "+f"(d3)                              \
        : "r"(a0), "r"(a1), "r"(a2), "r"(a3), "r"(b0), "r"(b1))

#define LDSM4(r0, r1, r2, r3, addr)                                           \
    asm volatile(                                                             \
        "ldmatrix.sync.aligned.m8n8.x4.shared.b16 {%0,%1,%2,%3},[%4];\n"      \
        : "=r"(r0), "=r"(r1), "=r"(r2), "=r"(r3)                              \
        : "r"(addr))

#define LDSM4T(r0, r1, r2, r3, addr)                                          \
    asm volatile(                                                             \
        "ldmatrix.sync.aligned.m8n8.x4.trans.shared.b16 {%0,%1,%2,%3},[%4];\n"\
        : "=r"(r0), "=r"(r1), "=r"(r2), "=r"(r3)                              \
        : "r"(addr))

#define CP16(d, s)                                                            \
    asm volatile("cp.async.cg.shared.global [%0], [%1], 16;\n"                \
                 :: "r"(d), "l"(s))
#define CPCOMMIT asm volatile("cp.async.commit_group;\n")
#define CPWAIT1  asm volatile("cp.async.wait_group 1;\n")
#define CPWAIT0  asm volatile("cp.async.wait_group 0;\n")

__device__ __forceinline__ float ex2f(float x) {
    float r;
    asm("ex2.approx.ftz.f32 %0, %1;" : "=f"(r) : "f"(x));
    return r;
}

/* the REAL f16x2 MUFU exp2: one instruction per 2 elements
   (h2exp2 from cuda_fp16.h lowers to an accuracy-hardened emulation with
    heavy FMA/ALU cost — that was the R6/R8/R14 regression mechanism) */
__device__ __forceinline__ unsigned ex2h2(__half2 x) {
    unsigned r;
    asm("ex2.approx.f16x2 %0, %1;" : "=r"(r) : "r"(*(unsigned*)&x));
    return r;
}

#define ONESH2 0x3C003C00u   /* half2 {1.0, 1.0} */
#define LDS 40               /* smem row stride in halfs (80B) */
#define STG_B (TK * LDS * 2) /* bytes per K/V stage: 5120 */

__global__ __launch_bounds__(256, 3) void attn_kernel(
    const float* __restrict__ q,   // [B, S, C] fp32
    float* __restrict__ out) {     // [B, S, C] fp32
    int qt = blockIdx.x, h = blockIdx.y, b = blockIdx.z;

    __shared__ __align__(16) __half Qs[TQ * LDS];
    __shared__ __align__(16) __half Ks[3][TK * LDS];
    __shared__ __align__(16) __half Vh[3][TK * LDS];

    int tid  = threadIdx.x;
    int warp = tid >> 5;
    int lane = tid & 31;
    int ln   = lane >> 2;
    int lq   = (lane & 3) * 2;

    const __half* kg = g_kh + (size_t)b * SQ * Cc + h * HD;
    const __half* vg = g_vh + (size_t)b * SQ * Cc + h * HD;

    // ---- cp.async staging ----
    int srow = tid >> 2;
    int scol = (tid & 3) * 8;
    unsigned dk0 = (unsigned)__cvta_generic_to_shared(&Ks[0][srow * LDS + scol]);
    unsigned dv0 = (unsigned)__cvta_generic_to_shared(&Vh[0][srow * LDS + scol]);

    // prefetch tiles 0 and 1
    {
        size_t g0 = (size_t)srow * Cc + scol;
        CP16(dk0, kg + g0);
        CP16(dv0, vg + g0);
        CPCOMMIT;
        size_t g1 = ((size_t)(TK + srow)) * Cc + scol;
        CP16(dk0 + STG_B, kg + g1);
        CP16(dv0 + STG_B, vg + g1);
        CPCOMMIT;
    }

    // ---- load Q tile ----
    const float* qg = q + ((size_t)(b * SQ + qt * TQ)) * Cc + h * HD;
#pragma unroll
    for (int i = 0; i < 4; i++) {
        int idx = tid + i * 256;
        int r = idx >> 3, cp = (idx & 7) * 4;
        float4 v = *(const float4*)(qg + (size_t)r * Cc + cp);
        __half2 h0 = __floats2half2_rn(v.x * QSCALE, v.y * QSCALE);
        __half2 h1 = __floats2half2_rn(v.z * QSCALE, v.w * QSCALE);
        *(__half2*)&Qs[r * LDS + cp]     = h0;
        *(__half2*)&Qs[r * LDS + cp + 2] = h1;
    }
    __syncthreads();

    // ---- Q A-frags ----
    unsigned qa[2][4];
    {
        int r0 = warp * 16 + ln;
#pragma unroll
        for (int s = 0; s < 2; s++) {
            qa[s][0] = *(const unsigned*)&Qs[r0 * LDS + lq + s * 16];
            qa[s][1] = *(const unsigned*)&Qs[(r0 + 8) * LDS + lq + s * 16];
            qa[s][2] = *(const unsigned*)&Qs[r0 * LDS + lq + 8 + s * 16];
            qa[s][3] = *(const unsigned*)&Qs[(r0 + 8) * LDS + lq + 8 + s * 16];
        }
    }

    // ---- ldmatrix bases (stage 0) ----
    int krow = ((lane >> 4) << 3) + (lane & 7);
    int kcol = ((lane >> 3) & 1) * 8;
    unsigned kfb0 = (unsigned)__cvta_generic_to_shared(&Ks[0][krow * LDS + kcol]);
    int mi  = lane >> 3;
    int vro = ((mi & 1) << 3) + (lane & 7);
    int vco = (mi >> 1) << 3;
    unsigned vfb0 = (unsigned)__cvta_generic_to_shared(&Vh[0][vro * LDS + vco]);

    float oc[4][4] = {};
    float lc[4]    = {};
    float mr0, mr1;                 // row-max bias (set in peeled tile 0)
    int cur, pre;

#define QKS(jp, s)                                                            \
    do {                                                                      \
        unsigned b0, b1, b2, b3;                                              \
        LDSM4(b0, b1, b2, b3,                                                 \
              kf + (unsigned)((jp) * (16 * LDS * 2) + (s) * 32));             \
        MMA16816(sc[2*(jp)][0], sc[2*(jp)][1], sc[2*(jp)][2], sc[2*(jp)][3],  \
                 qa[s][0], qa[s][1], qa[s][2], qa[s][3], b0, b1);             \
        MMA16816(sc[2*(jp)+1][0], sc[2*(jp)+1][1], sc[2*(jp)+1][2],           \
                 sc[2*(jp)+1][3],                                             \
                 qa[s][0], qa[s][1], qa[s][2], qa[s][3], b2, b3);             \
    } while (0)

/* f32 exp (tile 0 only), centered by freshly computed row max */
#define EXPT0(t)                                                              \
    do {                                                                      \
        float e0 = ex2f(sc[2*(t)][0] - mr0);                                  \
        float e1 = ex2f(sc[2*(t)][1] - mr0);                                  \
        float e2 = ex2f(sc[2*(t)][2] - mr1);                                  \
        float e3 = ex2f(sc[2*(t)][3] - mr1);                                  \
        float g0 = ex2f(sc[2*(t)+1][0] - mr0);                                \
        float g1 = ex2f(sc[2*(t)+1][1] - mr0);                                \
        float g2 = ex2f(sc[2*(t)+1][2] - mr1);                                \
        float g3 = ex2f(sc[2*(t)+1][3] - mr1);                                \
        __half2 d;                                                            \
        d = __floats2half2_rn(e0, e1); pa[t][0] = *(unsigned*)&d;             \
        d = __floats2half2_rn(e2, e3); pa[t][1] = *(unsigned*)&d;             \
        d = __floats2half2_rn(g0, g1); pa[t][2] = *(unsigned*)&d;             \
        d = __floats2half2_rn(g2, g3); pa[t][3] = *(unsigned*)&d;             \
    } while (0)

/* raw ex2.approx.f16x2 (tiles 1..): args centered near 0 by mr -> fp16-safe;
   centering FADDs run on the near-idle fma pipe; MUFU count halved */
#define EXPTH(t)                                                              \
    do {                                                                      \
        pa[t][0] = ex2h2(__floats2half2_rn(sc[2*(t)][0] - mr0,                \
                                           sc[2*(t)][1] - mr0));              \
        pa[t][1] = ex2h2(__floats2half2_rn(sc[2*(t)][2] - mr1,                \
                                           sc[2*(t)][3] - mr1));              \
        pa[t][2] = ex2h2(__floats2half2_rn(sc[2*(t)+1][0] - mr0,              \
                                           sc[2*(t)+1][1] - mr0));            \
        pa[t][3] = ex2h2(__floats2half2_rn(sc[2*(t)+1][2] - mr1,              \
                                           sc[2*(t)+1][3] - mr1));            \
    } while (0)

#define LMMA(t)                                                               \
    MMA16816(lc[0], lc[1], lc[2], lc[3],                                      \
             pa[t][0], pa[t][1], pa[t][2], pa[t][3], ONESH2, ONESH2)

#define PVT(pair, t)                                                          \
    do {                                                                      \
        unsigned r0, r1, r2, r3;                                              \
        LDSM4T(r0, r1, r2, r3,                                                \
               vf + (unsigned)((t) * (16 * LDS * 2) + (pair) * 32));          \
        MMA16816(oc[2*(pair)][0], oc[2*(pair)][1], oc[2*(pair)][2],           \
                 oc[2*(pair)][3],                                             \
                 pa[t][0], pa[t][1], pa[t][2], pa[t][3], r0, r1);             \
        MMA16816(oc[2*(pair)+1][0], oc[2*(pair)+1][1], oc[2*(pair)+1][2],     \
                 oc[2*(pair)+1][3],                                           \
                 pa[t][0], pa[t][1], pa[t][2], pa[t][3], r2, r3);             \
    } while (0)

#define PVBLOCK                                                               \
    do {                                                                      \
        PVT(0, 0); PVT(1, 0); LMMA(0);                                        \
        PVT(0, 1); PVT(1, 1); LMMA(1);                                        \
        PVT(0, 2); PVT(1, 2); LMMA(2);                                        \
        PVT(0, 3); PVT(1, 3); LMMA(3);                                        \
    } while (0)

    // ================= peeled tile 0 (computes row-max bias) =================
    {
        CPWAIT1;
        __syncthreads();
        // prefetch tile 2 into stage 2
        {
            size_t go = ((size_t)(2 * TK + srow)) * Cc + scol;
            CP16(dk0 + 2 * STG_B, kg + go);
            CP16(dv0 + 2 * STG_B, vg + go);
            CPCOMMIT;
        }
        unsigned kf = kfb0;
        unsigned vf = vfb0;

        float sc[8][4];
#pragma unroll
        for (int j = 0; j < 8; j++)
#pragma unroll
            for (int c = 0; c < 4; c++) sc[j][c] = -MFIX;
        unsigned pa[4][4];

        QKS(0, 0); QKS(1, 0); QKS(2, 0); QKS(3, 0);
        QKS(0, 1); QKS(1, 1); QKS(2, 1); QKS(3, 1);

        float mx0 = -1e30f, mx1 = -1e30f;
#pragma unroll
        for (int j = 0; j < 8; j++) {
            mx0 = fmaxf(mx0, fmaxf(sc[j][0], sc[j][1]));
            mx1 = fmaxf(mx1, fmaxf(sc[j][2], sc[j][3]));
        }
        mx0 = fmaxf(mx0, __shfl_xor_sync(0xffffffffu, mx0, 1));
        mx0 = fmaxf(mx0, __shfl_xor_sync(0xffffffffu, mx0, 2));
        mx1 = fmaxf(mx1, __shfl_xor_sync(0xffffffffu, mx1, 1));
        mx1 = fmaxf(mx1, __shfl_xor_sync(0xffffffffu, mx1, 2));
        mr0 = mx0; mr1 = mx1;

        EXPT0(0); EXPT0(1); EXPT0(2); EXPT0(3);
        PVBLOCK;
        cur = 1; pre = 0;
    }

    // ================= main loop: tiles 1..15, branchless =================
    for (int kt = 1; kt < NIT; kt++) {
        if (kt == NIT - 1) { CPWAIT0; } else { CPWAIT1; }
        __syncthreads();   // tile kt visible; stage 'pre' readers done

        if (kt + 2 < NIT) {
            size_t go = ((size_t)((kt + 2) * TK + srow)) * Cc + scol;
            unsigned off = (unsigned)(pre * STG_B);
            CP16(dk0 + off, kg + go);
            CP16(dv0 + off, vg + go);
            CPCOMMIT;
        }
        unsigned kf = kfb0 + (unsigned)(cur * STG_B);
        unsigned vf = vfb0 + (unsigned)(cur * STG_B);

        float sc[8][4];
#pragma unroll
        for (int j = 0; j < 8; j++)
#pragma unroll
            for (int c = 0; c < 4; c++) sc[j][c] = -MFIX;
        unsigned pa[4][4];

        // ---- QK: s-outer (same-accumulator distance 8), exps threaded ----
        QKS(0, 0); QKS(1, 0); QKS(2, 0); QKS(3, 0);
        QKS(0, 1); QKS(1, 1);
        EXPTH(0);
        QKS(2, 1);
        EXPTH(1);
        QKS(3, 1);
        EXPTH(2);
        EXPTH(3);

        PVBLOCK;

        cur = (cur == 2) ? 0 : cur + 1;
        pre = (pre == 2) ? 0 : pre + 1;
    }

    // ---- epilogue (2^-(MFIX+mr) factor cancels in oc/lc) ----
    float il0 = 1.0f / lc[0];
    float il1 = 1.0f / lc[2];
    int gr0 = qt * TQ + warp * 16 + ln;
    size_t ob = ((size_t)b * SQ) * Cc + h * HD;
#pragma unroll
    for (int n = 0; n < 4; n++) {
        int c0 = n * 8 + lq;
        float2 v0 = make_float2(oc[n][0] * il0, oc[n][1] * il0);
        float2 v1 = make_float2(oc[n][2] * il1, oc[n][3] * il1);
        *(float2*)&out[ob + (size_t)gr0 * Cc + c0]       = v0;
        *(float2*)&out[ob + (size_t)(gr0 + 8) * Cc + c0] = v1;
    }
}

// ---------------------------------------------------------------------------
extern "C" void kernel_launch(void* const* d_in, const int* in_sizes, int n_in,
                              void* d_out, int out_size) {
    const float* query  = (const float*)d_in[0];
    const float* key_in = (const float*)d_in[1];
    const float* value  = (const float*)d_in[2];
    const float* ck     = (const float*)d_in[3];
    const float* cb     = (const float*)d_in[4];
    float* out = (float*)d_out;

    dwconv_kernel<<<1024, 256>>>(key_in, value, ck, cb);

    dim3 grid(SQ / TQ, NH, Bn);
    attn_kernel<<<grid, 256>>>(query, out);
}

// round 17
// speedup vs baseline: 1.7319x; 1.0418x over previous
#include <cuda_runtime.h>
#include <cuda_fp16.h>

#define Bn 16
#define Cc 256
#define NH 8
#define HD 32
#define SQ 1024
#define TQ 128
#define TK 64
#define NIT (SQ / TK)
#define QSCALE 0.25507021480342156f /* 32^-0.5 * log2(e) */
#define MFIX 12.0f                  /* fixed softmax bias (log2 domain) */

// conv outputs, fp16
__device__ __half g_kh[Bn * SQ * Cc];
__device__ __half g_vh[Bn * SQ * Cc];

// ---------------------------------------------------------------------------
// Depthwise dilated 3x3 conv (dilation 2, SAME). Each thread computes
// 4 channels x 4 y-outputs (same parity, step 2).
// ---------------------------------------------------------------------------
__global__ __launch_bounds__(256) void dwconv_kernel(
    const float* __restrict__ kin,
    const float* __restrict__ vin,
    const float* __restrict__ ker,     // [3,3,1,C]
    const float* __restrict__ bias) {  // [C]
    int t    = blockIdx.x * 256 + threadIdx.x;
    int c    = (t & 63) * 4;
    int idx2 = t >> 6;
    int x  = idx2 & 31;
    int yg = (idx2 >> 5) & 7;
    int b  = idx2 >> 8;
    int p  = yg & 1;
    int g  = yg >> 1;

    float4 w[9];
#pragma unroll
    for (int ti = 0; ti < 9; ti++) w[ti] = *(const float4*)(ker + ti * Cc + c);
    float4 bi = *(const float4*)(bias + c);
    float4 ka[4], va[4];
#pragma unroll
    for (int i = 0; i < 4; i++) { ka[i] = bi; va[i] = bi; }

#pragma unroll
    for (int j = 0; j < 3; j++) {
        int xx = x + 2 * j - 2;
        if ((unsigned)xx >= 32u) continue;
#pragma unroll
        for (int r = 0; r < 6; r++) {
            int ry = 4 * g + r - 1;
            if ((unsigned)ry >= 16u) continue;
            int yy = p + 2 * ry;
            size_t idx = ((size_t)((b * 32 + yy) * 32 + xx)) * Cc + c;
            float4 kv = *(const float4*)(kin + idx);
            float4 vv = *(const float4*)(vin + idx);
#pragma unroll
            for (int i = 0; i < 4; i++) {
                int ti = r - i;
                if (ti < 0 || ti > 2) continue;
                float4 ww = w[ti * 3 + j];
                ka[i].x = fmaf(kv.x, ww.x, ka[i].x);
                ka[i].y = fmaf(kv.y, ww.y, ka[i].y);
                ka[i].z = fmaf(kv.z, ww.z, ka[i].z);
                ka[i].w = fmaf(kv.w, ww.w, ka[i].w);
                va[i].x = fmaf(vv.x, ww.x, va[i].x);
                va[i].y = fmaf(vv.y, ww.y, va[i].y);
                va[i].z = fmaf(vv.z, ww.z, va[i].z);
                va[i].w = fmaf(vv.w, ww.w, va[i].w);
            }
        }
    }
#pragma unroll
    for (int i = 0; i < 4; i++) {
        int yy = p + 2 * (4 * g + i);
        size_t o = ((size_t)(b * 1024 + yy * 32 + x)) * Cc + c;
        __half2 k0 = __floats2half2_rn(ka[i].x, ka[i].y);
        __half2 k1 = __floats2half2_rn(ka[i].z, ka[i].w);
        __half2 v0 = __floats2half2_rn(va[i].x, va[i].y);
        __half2 v1 = __floats2half2_rn(va[i].z, va[i].w);
        *(__half2*)(g_kh + o)     = k0;
        *(__half2*)(g_kh + o + 2) = k1;
        *(__half2*)(g_vh + o)     = v0;
        *(__half2*)(g_vh + o + 2) = v1;
    }
}

// ---------------------------------------------------------------------------
#define MMA16816(d0, d1, d2, d3, a0, a1, a2, a3, b0, b1)                      \
    asm volatile(                                                             \
        "mma.sync.aligned.m16n8k16.row.col.f32.f16.f16.f32 "                  \
        "{%0,%1,%2,%3},{%4,%5,%6,%7},{%8,%9},{%0,%1,%2,%3};\n"                \
        : "+f"(d0), "+f"(d1), "+f"(d2), "+f"(d3)                              \
        : "r"(a0), "r"(a1), "r"(a2), "r"(a3), "r"(b0), "r"(b1))

#define LDSM4(r0, r1, r2, r3, addr)                                           \
    asm volatile(                                                             \
        "ldmatrix.sync.aligned.m8n8.x4.shared.b16 {%0,%1,%2,%3},[%4];\n"      \
        : "=r"(r0), "=r"(r1), "=r"(r2), "=r"(r3)                              \
        : "r"(addr))

#define LDSM4T(r0, r1, r2, r3, addr)                                          \
    asm volatile(                                                             \
        "ldmatrix.sync.aligned.m8n8.x4.trans.shared.b16 {%0,%1,%2,%3},[%4];\n"\
        : "=r"(r0), "=r"(r1), "=r"(r2), "=r"(r3)                              \
        : "r"(addr))

#define CP16(d, s)                                                            \
    asm volatile("cp.async.cg.shared.global [%0], [%1], 16;\n"                \
                 :: "r"(d), "l"(s))
#define CPCOMMIT asm volatile("cp.async.commit_group;\n")
#define CPWAIT1  asm volatile("cp.async.wait_group 1;\n")
#define CPWAIT0  asm volatile("cp.async.wait_group 0;\n")

__device__ __forceinline__ float ex2f(float x) {
    float r;
    asm("ex2.approx.ftz.f32 %0, %1;" : "=f"(r) : "f"(x));
    return r;
}

/* raw f16x2 MUFU exp2: one instruction per 2 elements */
__device__ __forceinline__ unsigned ex2h2(__half2 x) {
    unsigned r;
    asm("ex2.approx.f16x2 %0, %1;" : "=r"(r) : "r"(*(unsigned*)&x));
    return r;
}

#define ONESH2 0x3C003C00u   /* half2 {1.0, 1.0} */
#define LDS 40               /* smem row stride in halfs (80B) */
#define STG_B (TK * LDS * 2) /* bytes per K/V stage: 5120 */

// ---------------------------------------------------------------------------
// Attention: 128 threads (4 warps), M=32 rows/warp. Per warp-tile the
// 16 LDSM B-fragments feed 72 MMAs (vs 36 at M=16) -> per-CTA smem read
// traffic for B operands halves. V fragments cached in registers and reused
// across both m-tiles.
// ---------------------------------------------------------------------------
__global__ __launch_bounds__(128, 3) void attn_kernel(
    const float* __restrict__ q,   // [B, S, C] fp32
    float* __restrict__ out) {     // [B, S, C] fp32
    int qt = blockIdx.x, h = blockIdx.y, b = blockIdx.z;

    __shared__ __align__(16) __half Qs[TQ * LDS];
    __shared__ __align__(16) __half Ks[3][TK * LDS];
    __shared__ __align__(16) __half Vh[3][TK * LDS];

    int tid  = threadIdx.x;
    int warp = tid >> 5;
    int lane = tid & 31;
    int ln   = lane >> 2;
    int lq   = (lane & 3) * 2;

    const __half* kg = g_kh + (size_t)b * SQ * Cc + h * HD;
    const __half* vg = g_vh + (size_t)b * SQ * Cc + h * HD;

    // ---- cp.async staging: 128 threads, 2 chunks each per tensor ----
    // tile data = 64 rows x 64B (4x16B chunks) = 256 chunks
    unsigned dk0 = (unsigned)__cvta_generic_to_shared(&Ks[0][0]);
    unsigned dv0 = (unsigned)__cvta_generic_to_shared(&Vh[0][0]);
    int r0s = tid >> 2, c0s = (tid & 3) * 16;            // chunk 0: rows 0..31
    int r1s = (tid + 128) >> 2, c1s = c0s;               // chunk 1: rows 32..63
    unsigned so0 = (unsigned)(r0s * 80 + c0s);
    unsigned so1 = (unsigned)(r1s * 80 + c1s);
    size_t  go0 = (size_t)r0s * Cc + (c0s >> 1);         // half units
    size_t  go1 = (size_t)r1s * Cc + (c1s >> 1);

#define STAGE_LOAD(stg, tile)                                                 \
    do {                                                                      \
        size_t tb = (size_t)(tile) * TK * Cc;                                 \
        unsigned ob = (unsigned)((stg) * STG_B);                              \
        CP16(dk0 + ob + so0, kg + tb + go0);                                  \
        CP16(dk0 + ob + so1, kg + tb + go1);                                  \
        CP16(dv0 + ob + so0, vg + tb + go0);                                  \
        CP16(dv0 + ob + so1, vg + tb + go1);                                  \
        CPCOMMIT;                                                             \
    } while (0)

    STAGE_LOAD(0, 0);
    STAGE_LOAD(1, 1);

    // ---- load Q tile (fp32 -> fp16, pre-scaled) ----
    const float* qg = q + ((size_t)(b * SQ + qt * TQ)) * Cc + h * HD;
#pragma unroll
    for (int i = 0; i < 8; i++) {
        int idx = tid + i * 128;
        int r = idx >> 3, cp = (idx & 7) * 4;
        float4 v = *(const float4*)(qg + (size_t)r * Cc + cp);
        __half2 h0 = __floats2half2_rn(v.x * QSCALE, v.y * QSCALE);
        __half2 h1 = __floats2half2_rn(v.z * QSCALE, v.w * QSCALE);
        *(__half2*)&Qs[r * LDS + cp]     = h0;
        *(__half2*)&Qs[r * LDS + cp + 2] = h1;
    }
    __syncthreads();

    // ---- Q A-frags: 2 m-tiles x 2 k-steps ----
    unsigned qa[2][2][4];
#pragma unroll
    for (int m = 0; m < 2; m++) {
        int r0 = warp * 32 + m * 16 + ln;
#pragma unroll
        for (int s = 0; s < 2; s++) {
            qa[m][s][0] = *(const unsigned*)&Qs[r0 * LDS + lq + s * 16];
            qa[m][s][1] = *(const unsigned*)&Qs[(r0 + 8) * LDS + lq + s * 16];
            qa[m][s][2] = *(const unsigned*)&Qs[r0 * LDS + lq + 8 + s * 16];
            qa[m][s][3] = *(const unsigned*)&Qs[(r0 + 8) * LDS + lq + 8 + s * 16];
        }
    }

    // ---- ldmatrix bases (stage 0) ----
    int krow = ((lane >> 4) << 3) + (lane & 7);
    int kcol = ((lane >> 3) & 1) * 8;
    unsigned kfb0 = (unsigned)__cvta_generic_to_shared(&Ks[0][krow * LDS + kcol]);
    int mi  = lane >> 3;
    int vro = ((mi & 1) << 3) + (lane & 7);
    int vco = (mi >> 1) << 3;
    unsigned vfb0 = (unsigned)__cvta_generic_to_shared(&Vh[0][vro * LDS + vco]);

    float oc[2][4][4] = {};
    float lc[2][4]    = {};
    float mr[2][2];              // row-max bias per m-tile (set in peeled tile 0)
    int cur, pre;

/* QK step: one LDSM4 feeds 4 MMAs (both m-tiles) */
#define QKS(jp, s)                                                            \
    do {                                                                      \
        unsigned b0, b1, b2, b3;                                              \
        LDSM4(b0, b1, b2, b3,                                                 \
              kf + (unsigned)((jp) * (16 * LDS * 2) + (s) * 32));             \
        MMA16816(sc[2*(jp)][0], sc[2*(jp)][1], sc[2*(jp)][2], sc[2*(jp)][3],  \
                 qa[0][s][0], qa[0][s][1], qa[0][s][2], qa[0][s][3], b0, b1); \
        MMA16816(sc[2*(jp)+1][0], sc[2*(jp)+1][1], sc[2*(jp)+1][2],           \
                 sc[2*(jp)+1][3],                                             \
                 qa[0][s][0], qa[0][s][1], qa[0][s][2], qa[0][s][3], b2, b3); \
        MMA16816(sc[8+2*(jp)][0], sc[8+2*(jp)][1], sc[8+2*(jp)][2],           \
                 sc[8+2*(jp)][3],                                             \
                 qa[1][s][0], qa[1][s][1], qa[1][s][2], qa[1][s][3], b0, b1); \
        MMA16816(sc[8+2*(jp)+1][0], sc[8+2*(jp)+1][1], sc[8+2*(jp)+1][2],     \
                 sc[8+2*(jp)+1][3],                                           \
                 qa[1][s][0], qa[1][s][1], qa[1][s][2], qa[1][s][3], b2, b3); \
    } while (0)

/* f32 exp (tile 0 only) for m-tile m */
#define EXPT0(m, t)                                                           \
    do {                                                                      \
        float e0 = ex2f(sc[(m)*8+2*(t)][0] - mr[m][0]);                       \
        float e1 = ex2f(sc[(m)*8+2*(t)][1] - mr[m][0]);                       \
        float e2 = ex2f(sc[(m)*8+2*(t)][2] - mr[m][1]);                       \
        float e3 = ex2f(sc[(m)*8+2*(t)][3] - mr[m][1]);                       \
        float g0 = ex2f(sc[(m)*8+2*(t)+1][0] - mr[m][0]);                     \
        float g1 = ex2f(sc[(m)*8+2*(t)+1][1] - mr[m][0]);                     \
        float g2 = ex2f(sc[(m)*8+2*(t)+1][2] - mr[m][1]);                     \
        float g3 = ex2f(sc[(m)*8+2*(t)+1][3] - mr[m][1]);                     \
        __half2 d;                                                            \
        d = __floats2half2_rn(e0, e1); pa[t][0] = *(unsigned*)&d;             \
        d = __floats2half2_rn(e2, e3); pa[t][1] = *(unsigned*)&d;             \
        d = __floats2half2_rn(g0, g1); pa[t][2] = *(unsigned*)&d;             \
        d = __floats2half2_rn(g2, g3); pa[t][3] = *(unsigned*)&d;             \
    } while (0)

/* raw f16x2 exp (tiles 1..) for m-tile m */
#define EXPTH(m, t)                                                           \
    do {                                                                      \
        pa[t][0] = ex2h2(__floats2half2_rn(sc[(m)*8+2*(t)][0] - mr[m][0],     \
                                           sc[(m)*8+2*(t)][1] - mr[m][0]));   \
        pa[t][1] = ex2h2(__floats2half2_rn(sc[(m)*8+2*(t)][2] - mr[m][1],     \
                                           sc[(m)*8+2*(t)][3] - mr[m][1]));   \
        pa[t][2] = ex2h2(__floats2half2_rn(sc[(m)*8+2*(t)+1][0] - mr[m][0],   \
                                           sc[(m)*8+2*(t)+1][1] - mr[m][0])); \
        pa[t][3] = ex2h2(__floats2half2_rn(sc[(m)*8+2*(t)+1][2] - mr[m][1],   \
                                           sc[(m)*8+2*(t)+1][3] - mr[m][1])); \
    } while (0)

#define LMMA(m, t)                                                            \
    MMA16816(lc[m][0], lc[m][1], lc[m][2], lc[m][3],                          \
             pa[t][0], pa[t][1], pa[t][2], pa[t][3], ONESH2, ONESH2)

/* V B-frags loaded ONCE per tile into registers, reused by both m-tiles */
#define VLOAD                                                                 \
    do {                                                                      \
        _Pragma("unroll")                                                     \
        for (int t = 0; t < 4; t++)                                           \
            _Pragma("unroll")                                                 \
            for (int pr = 0; pr < 2; pr++)                                    \
                LDSM4T(vb[t*2+pr][0], vb[t*2+pr][1], vb[t*2+pr][2],           \
                       vb[t*2+pr][3],                                         \
                       vf + (unsigned)(t * (16 * LDS * 2) + pr * 32));        \
    } while (0)

#define PVM(m)                                                                \
    do {                                                                      \
        _Pragma("unroll")                                                     \
        for (int t = 0; t < 4; t++) {                                         \
            MMA16816(oc[m][0][0], oc[m][0][1], oc[m][0][2], oc[m][0][3],      \
                     pa[t][0], pa[t][1], pa[t][2], pa[t][3],                  \
                     vb[t*2][0], vb[t*2][1]);                                 \
            MMA16816(oc[m][1][0], oc[m][1][1], oc[m][1][2], oc[m][1][3],      \
                     pa[t][0], pa[t][1], pa[t][2], pa[t][3],                  \
                     vb[t*2][2], vb[t*2][3]);                                 \
            MMA16816(oc[m][2][0], oc[m][2][1], oc[m][2][2], oc[m][2][3],      \
                     pa[t][0], pa[t][1], pa[t][2], pa[t][3],                  \
                     vb[t*2+1][0], vb[t*2+1][1]);                             \
            MMA16816(oc[m][3][0], oc[m][3][1], oc[m][3][2], oc[m][3][3],      \
                     pa[t][0], pa[t][1], pa[t][2], pa[t][3],                  \
                     vb[t*2+1][2], vb[t*2+1][3]);                             \
            LMMA(m, t);                                                       \
        }                                                                     \
    } while (0)

    // ================= peeled tile 0 (computes row-max bias) =================
    {
        CPWAIT1;
        __syncthreads();
        STAGE_LOAD(2, 2);
        unsigned kf = kfb0;
        unsigned vf = vfb0;

        float sc[16][4];
#pragma unroll
        for (int j = 0; j < 16; j++)
#pragma unroll
            for (int c = 0; c < 4; c++) sc[j][c] = -MFIX;

        QKS(0, 0); QKS(1, 0); QKS(2, 0); QKS(3, 0);
        QKS(0, 1); QKS(1, 1); QKS(2, 1); QKS(3, 1);

#pragma unroll
        for (int m = 0; m < 2; m++) {
            float mx0 = -1e30f, mx1 = -1e30f;
#pragma unroll
            for (int j = 0; j < 8; j++) {
                mx0 = fmaxf(mx0, fmaxf(sc[m*8+j][0], sc[m*8+j][1]));
                mx1 = fmaxf(mx1, fmaxf(sc[m*8+j][2], sc[m*8+j][3]));
            }
            mx0 = fmaxf(mx0, __shfl_xor_sync(0xffffffffu, mx0, 1));
            mx0 = fmaxf(mx0, __shfl_xor_sync(0xffffffffu, mx0, 2));
            mx1 = fmaxf(mx1, __shfl_xor_sync(0xffffffffu, mx1, 1));
            mx1 = fmaxf(mx1, __shfl_xor_sync(0xffffffffu, mx1, 2));
            mr[m][0] = mx0; mr[m][1] = mx1;
        }

        unsigned vb[8][4];
        VLOAD;
#pragma unroll
        for (int m = 0; m < 2; m++) {
            unsigned pa[4][4];
            EXPT0(m, 0); EXPT0(m, 1); EXPT0(m, 2); EXPT0(m, 3);
            PVM(m);
        }
        cur = 1; pre = 0;
    }

    // ================= main loop: tiles 1..15, branchless =================
    for (int kt = 1; kt < NIT; kt++) {
        if (kt == NIT - 1) { CPWAIT0; } else { CPWAIT1; }
        __syncthreads();   // tile kt visible; stage 'pre' readers done

        if (kt + 2 < NIT) STAGE_LOAD(pre, kt + 2);
        unsigned kf = kfb0 + (unsigned)(cur * STG_B);
        unsigned vf = vfb0 + (unsigned)(cur * STG_B);

        float sc[16][4];
#pragma unroll
        for (int j = 0; j < 16; j++)
#pragma unroll
            for (int c = 0; c < 4; c++) sc[j][c] = -MFIX;

        QKS(0, 0); QKS(1, 0); QKS(2, 0); QKS(3, 0);
        QKS(0, 1); QKS(1, 1); QKS(2, 1); QKS(3, 1);

        unsigned vb[8][4];
        VLOAD;
#pragma unroll
        for (int m = 0; m < 2; m++) {
            unsigned pa[4][4];
            EXPTH(m, 0); EXPTH(m, 1); EXPTH(m, 2); EXPTH(m, 3);
            PVM(m);
        }

        cur = (cur == 2) ? 0 : cur + 1;
        pre = (pre == 2) ? 0 : pre + 1;
    }

    // ---- epilogue (2^-(MFIX+mr) factor cancels in oc/lc) ----
    size_t ob = ((size_t)b * SQ) * Cc + h * HD;
#pragma unroll
    for (int m = 0; m < 2; m++) {
        float il0 = 1.0f / lc[m][0];
        float il1 = 1.0f / lc[m][2];
        int gr0 = qt * TQ + warp * 32 + m * 16 + ln;
#pragma unroll
        for (int n = 0; n < 4; n++) {
            int c0 = n * 8 + lq;
            float2 v0 = make_float2(oc[m][n][0] * il0, oc[m][n][1] * il0);
            float2 v1 = make_float2(oc[m][n][2] * il1, oc[m][n][3] * il1);
            *(float2*)&out[ob + (size_t)gr0 * Cc + c0]       = v0;
            *(float2*)&out[ob + (size_t)(gr0 + 8) * Cc + c0] = v1;
        }
    }
}

// ---------------------------------------------------------------------------
extern "C" void kernel_launch(void* const* d_in, const int* in_sizes, int n_in,
                              void* d_out, int out_size) {
    const float* query  = (const float*)d_in[0];
    const float* key_in = (const float*)d_in[1];
    const float* value  = (const float*)d_in[2];
    const float* ck     = (const float*)d_in[3];
    const float* cb     = (const float*)d_in[4];
    float* out = (float*)d_out;

    dwconv_kernel<<<1024, 256>>>(key_in, value, ck, cb);

    dim3 grid(SQ / TQ, NH, Bn);
    attn_kernel<<<grid, 128>>>(query, out);
}